// round 9
// baseline (speedup 1.0000x reference)
#include <cuda_runtime.h>
#include <cuda_fp16.h>

#define NN 20000
#define NE 640000
#define F  128
#define UN 16                      // nodes per group (20000 % 16 == 0)
#define NGROUPS (NN / UN)          // 1250
#define LAYER_DSMEM (65536 + 16384) // W pairs 64KB + duplicated input tile 16KB
#define NB 160                     // scan blocks
#define CH 125                     // elements per scan block (160*125 = 20000)

// ---------------- scratch (device globals; no allocations allowed) ----------
__device__ __align__(16) __half g_xh[NN * F];    // x in half (gather source L1)
__device__ __align__(16) __half g_hh[NN * F];    // h1 in half (gather source L2)
__device__ float g_inv[NN];       // 1 / max(indegree, 1)
__device__ int   g_cnt[NN];       // zero-initialized; scanB re-zeroes each call
__device__ int   g_off[NN + 1];   // CSR offsets by dst
__device__ int   g_cur[NN];       // fill cursors
__device__ int   g_esrc[NE];      // src ids grouped by dst
__device__ int   g_bsum[NB];      // per-block count sums
__device__ int   g_is64;          // 1 if edge_index is int64, 0 if int32

// ---------------- packed f32x2 helpers ---------------------------------------
__device__ __forceinline__ unsigned long long ffma2(unsigned long long a,
                                                    unsigned long long b,
                                                    unsigned long long c) {
    unsigned long long d;
    asm("fma.rn.f32x2 %0, %1, %2, %3;" : "=l"(d) : "l"(a), "l"(b), "l"(c));
    return d;
}
__device__ __forceinline__ void unpack2(unsigned long long p, float& lo, float& hi) {
    asm("mov.b64 {%0, %1}, %2;" : "=f"(lo), "=f"(hi) : "l"(p));
}

// ---------------- prep: x->half + dtype detect --------------------------------
// int64 node ids < 2^31 have zero high words at odd int32 indices.
__global__ void k_prep(const int* __restrict__ ei32, const float4* __restrict__ x) {
    int i = blockIdx.x * blockDim.x + threadIdx.x;
    if (i < NN * F / 4) {
        float4 v = x[i];
        __half2* o = (__half2*)g_xh;
        o[2 * i + 0] = __floats2half2_rn(v.x, v.y);
        o[2 * i + 1] = __floats2half2_rn(v.z, v.w);
    }
    if (i < 32) {
        int v = 0;
#pragma unroll
        for (int j = 0; j < 4; ++j) v |= ei32[2 * (i + 32 * j) + 1];
#pragma unroll
        for (int d = 16; d; d >>= 1) v |= __shfl_xor_sync(0xffffffffu, v, d);
        if (i == 0) g_is64 = (v == 0) ? 1 : 0;
    }
}

// ---------------- CSR build: 4 edges per thread -------------------------------
__global__ void k_count(const void* __restrict__ ei) {
    int t = blockIdx.x * blockDim.x + threadIdx.x;
    if (t >= NE / 4) return;
    int d0, d1, d2, d3;
    if (g_is64) {
        const longlong2* p = (const longlong2*)ei;
        longlong2 a = p[(NE + 4 * t) / 2], b = p[(NE + 4 * t) / 2 + 1];
        d0 = (int)a.x; d1 = (int)a.y; d2 = (int)b.x; d3 = (int)b.y;
    } else {
        int4 a = ((const int4*)ei)[(NE + 4 * t) / 4];
        d0 = a.x; d1 = a.y; d2 = a.z; d3 = a.w;
    }
    if ((unsigned)d0 < NN) atomicAdd(&g_cnt[d0], 1);
    if ((unsigned)d1 < NN) atomicAdd(&g_cnt[d1], 1);
    if ((unsigned)d2 < NN) atomicAdd(&g_cnt[d2], 1);
    if ((unsigned)d3 < NN) atomicAdd(&g_cnt[d3], 1);
}

// ---------------- hierarchical scan (grid=160) --------------------------------
__global__ void __launch_bounds__(128) k_scanA() {
    int b = blockIdx.x, t = threadIdx.x, lane = t & 31, wid = t >> 5;
    __shared__ int ws[4];
    int c = (t < CH) ? g_cnt[b * CH + t] : 0;
#pragma unroll
    for (int d = 16; d; d >>= 1) c += __shfl_xor_sync(0xffffffffu, c, d);
    if (lane == 0) ws[wid] = c;
    __syncthreads();
    if (t == 0) g_bsum[b] = ws[0] + ws[1] + ws[2] + ws[3];
}

// B: block base = sum of earlier block sums; scan own chunk; re-zero g_cnt.
__global__ void __launch_bounds__(192) k_scanB() {
    int b = blockIdx.x, t = threadIdx.x, lane = t & 31, wid = t >> 5;
    __shared__ int bs[6];
    __shared__ int wsum[4];
    int v = (t < b) ? g_bsum[t] : 0;      // b <= 159 < 192 threads
#pragma unroll
    for (int d = 16; d; d >>= 1) v += __shfl_xor_sync(0xffffffffu, v, d);
    if (lane == 0) bs[wid] = v;
    __syncthreads();
    int base = bs[0] + bs[1] + bs[2] + bs[3] + bs[4] + bs[5];

    int i = b * CH + t;
    int c = (t < CH) ? g_cnt[i] : 0;
    int s = c;
#pragma unroll
    for (int d = 1; d < 32; d <<= 1) {
        int u = __shfl_up_sync(0xffffffffu, s, d);
        if (lane >= d) s += u;
    }
    if (lane == 31 && wid < 4) wsum[wid] = s;
    __syncthreads();
    int off = base;
#pragma unroll
    for (int w = 0; w < 4; ++w) off += (w < wid) ? wsum[w] : 0;
    if (t < CH) {
        int inc = off + s;
        g_off[i + 1] = inc;
        g_cur[i]     = inc - c;
        g_inv[i]     = 1.0f / (float)(c > 0 ? c : 1);
        g_cnt[i]     = 0;                  // ready for next call
    }
    if (b == 0 && t == 0) g_off[0] = 0;
}

__global__ void k_fill(const void* __restrict__ ei) {
    int t = blockIdx.x * blockDim.x + threadIdx.x;
    if (t >= NE / 4) return;
    int s0, s1, s2, s3, d0, d1, d2, d3;
    if (g_is64) {
        const longlong2* p = (const longlong2*)ei;
        longlong2 a = p[(4 * t) / 2],       b = p[(4 * t) / 2 + 1];
        longlong2 c = p[(NE + 4 * t) / 2],  d = p[(NE + 4 * t) / 2 + 1];
        s0 = (int)a.x; s1 = (int)a.y; s2 = (int)b.x; s3 = (int)b.y;
        d0 = (int)c.x; d1 = (int)c.y; d2 = (int)d.x; d3 = (int)d.y;
    } else {
        int4 a = ((const int4*)ei)[t];
        int4 c = ((const int4*)ei)[(NE + 4 * t) / 4];
        s0 = a.x; s1 = a.y; s2 = a.z; s3 = a.w;
        d0 = c.x; d1 = c.y; d2 = c.z; d3 = c.w;
    }
    if ((unsigned)d0 < NN && (unsigned)s0 < NN) g_esrc[atomicAdd(&g_cur[d0], 1)] = s0;
    if ((unsigned)d1 < NN && (unsigned)s1 < NN) g_esrc[atomicAdd(&g_cur[d1], 1)] = s1;
    if ((unsigned)d2 < NN && (unsigned)s2 < NN) g_esrc[atomicAdd(&g_cur[d2], 1)] = s2;
    if ((unsigned)d3 < NN && (unsigned)s3 < NN) g_esrc[atomicAdd(&g_cur[d3], 1)] = s3;
}

// ---------------- fused layer: gather+mean -> (W,b) FFMA2 -> relu -> out -----
// Phase A: 4 warps gather 4 nodes each (mean of half rows, f32 accum), write
//          duplicated (v,v) pairs straight into the smem input tile.
// Phase B: packed-f32x2 matmul; thread owns column pair (jp, jp+64) and 8 nodes.
// layer2=0: store relu result as half to g_hh.
// layer2=1: keep h2 in registers, project 128->2 with W3 (warp reduce), write out.
__global__ void __launch_bounds__(128) k_layer(
    const float* __restrict__ W,  const float* __restrict__ b,
    const float* __restrict__ W3, const float* __restrict__ b3,
    float* __restrict__ out, int layer2)
{
    extern __shared__ char dyn[];
    float2*             Wsp  = (float2*)dyn;              // [k][jp] pairs, 64KB
    float4*             Insd = (float4*)(dyn + 65536);    // duplicated inputs, 16KB
    unsigned long long* InsU = (unsigned long long*)Insd;
    __shared__ float2 part[4][8];

    int tid  = threadIdx.x;
    int wid  = tid >> 5, lane = tid & 31;
    int jp   = tid & 63;
    int u0   = (tid >> 6) * 8;

    for (int e = tid; e < F * 64; e += 128) {
        int k = e >> 6, j = e & 63;
        Wsp[e] = make_float2(W[k * F + j], W[k * F + j + 64]);
    }
    float bj0 = b[jp], bj1 = b[jp + 64];
    float2 w3a = make_float2(0.f, 0.f), w3b = make_float2(0.f, 0.f);
    float b30 = 0.f, b31 = 0.f;
    if (layer2) {
        w3a = ((const float2*)W3)[jp];
        w3b = ((const float2*)W3)[jp + 64];
        b30 = b3[0]; b31 = b3[1];
    }
    const unsigned long long* WsU = (const unsigned long long*)Wsp;
    const uint2* __restrict__ feat = layer2 ? (const uint2*)g_hh : (const uint2*)g_xh;

    for (int g = blockIdx.x; g < NGROUPS; g += gridDim.x) {
        int n0 = g * UN;
        __syncthreads();   // Wsp staged (1st iter) / prior Insd reads done

        // ---- Phase A: gather + mean, write duplicated pairs to smem --------
        for (int uu = 0; uu < 4; ++uu) {
            int node = n0 + wid * 4 + uu;
            int beg = g_off[node], end = g_off[node + 1];
            float4 acc = make_float4(0.f, 0.f, 0.f, 0.f);
            int e0 = beg;
            for (; e0 + 32 <= end; e0 += 32) {
                int myid = g_esrc[e0 + lane];
#pragma unroll 8
                for (int j = 0; j < 32; ++j) {
                    int s = __shfl_sync(0xffffffffu, myid, j);
                    uint2 r = feat[s * 32 + lane];
                    float2 a = __half22float2(*(__half2*)&r.x);
                    float2 c = __half22float2(*(__half2*)&r.y);
                    acc.x += a.x; acc.y += a.y; acc.z += c.x; acc.w += c.y;
                }
            }
            int n = end - e0;
            if (n) {
                int myid = (lane < n) ? g_esrc[e0 + lane] : 0;
                for (int j = 0; j < n; ++j) {
                    int s = __shfl_sync(0xffffffffu, myid, j);
                    uint2 r = feat[s * 32 + lane];
                    float2 a = __half22float2(*(__half2*)&r.x);
                    float2 c = __half22float2(*(__half2*)&r.y);
                    acc.x += a.x; acc.y += a.y; acc.z += c.x; acc.w += c.y;
                }
            }
            float inv = g_inv[node];
            int ui = wid * 4 + uu;                 // lane == k4
            Insd[ui * 64 + 2 * lane]     = make_float4(acc.x * inv, acc.x * inv,
                                                       acc.y * inv, acc.y * inv);
            Insd[ui * 64 + 2 * lane + 1] = make_float4(acc.z * inv, acc.z * inv,
                                                       acc.w * inv, acc.w * inv);
        }
        __syncthreads();

        // ---- Phase B: matmul -----------------------------------------------
        unsigned long long ac[8];
#pragma unroll
        for (int u = 0; u < 8; ++u) ac[u] = 0ULL;

#pragma unroll 2
        for (int k4 = 0; k4 < 32; ++k4) {
            unsigned long long w0 = WsU[(4 * k4 + 0) * 64 + jp];
            unsigned long long w1 = WsU[(4 * k4 + 1) * 64 + jp];
            unsigned long long w2 = WsU[(4 * k4 + 2) * 64 + jp];
            unsigned long long w3 = WsU[(4 * k4 + 3) * 64 + jp];
#pragma unroll
            for (int u = 0; u < 8; ++u) {
                const unsigned long long* p = &InsU[((u0 + u) * 64 + 2 * k4) * 2];
                ulonglong2 A = *(const ulonglong2*)p;        // (vx,vx) (vy,vy)
                ulonglong2 B = *(const ulonglong2*)(p + 2);  // (vz,vz) (vw,vw)
                ac[u] = ffma2(A.x, w0, ac[u]);
                ac[u] = ffma2(A.y, w1, ac[u]);
                ac[u] = ffma2(B.x, w2, ac[u]);
                ac[u] = ffma2(B.y, w3, ac[u]);
            }
        }

        // ---- epilogue -------------------------------------------------------
        if (!layer2) {
#pragma unroll
            for (int u = 0; u < 8; ++u) {
                float lo, hi;
                unpack2(ac[u], lo, hi);
                float r0 = fmaxf(lo + bj0, 0.f), r1 = fmaxf(hi + bj1, 0.f);
                int node = n0 + u0 + u;
                g_hh[node * F + jp]      = __float2half(r0);
                g_hh[node * F + jp + 64] = __float2half(r1);
            }
        } else {
#pragma unroll
            for (int u = 0; u < 8; ++u) {
                float lo, hi;
                unpack2(ac[u], lo, hi);
                float r0 = fmaxf(lo + bj0, 0.f), r1 = fmaxf(hi + bj1, 0.f);
                float o0 = r0 * w3a.x + r1 * w3b.x;
                float o1 = r0 * w3a.y + r1 * w3b.y;
#pragma unroll
                for (int d = 16; d; d >>= 1) {
                    o0 += __shfl_down_sync(0xffffffffu, o0, d);
                    o1 += __shfl_down_sync(0xffffffffu, o1, d);
                }
                if (lane == 0) part[wid][u] = make_float2(o0, o1);
            }
            __syncthreads();
            if (tid < 16) {                       // node n0+tid
                int wa = (tid < 8) ? 0 : 2;       // warps {0,1} own u0=0, {2,3} own u0=8
                int uu = tid & 7;
                float2 pa = part[wa][uu], pb = part[wa + 1][uu];
                out[(n0 + tid) * 2 + 0] = pa.x + pb.x + b30;
                out[(n0 + tid) * 2 + 1] = pa.y + pb.y + b31;
            }
        }
    }
}

// ---------------- launch -----------------------------------------------------
extern "C" void kernel_launch(void* const* d_in, const int* in_sizes, int n_in,
                              void* d_out, int out_size) {
    const float* x  = (const float*)d_in[0];
    const void*  ei = d_in[1];
    const float* W1 = (const float*)d_in[2];
    const float* b1 = (const float*)d_in[3];
    const float* W2 = (const float*)d_in[4];
    const float* b2 = (const float*)d_in[5];
    const float* W3 = (const float*)d_in[6];
    const float* b3 = (const float*)d_in[7];
    float* out = (float*)d_out;

    cudaFuncSetAttribute(k_layer, cudaFuncAttributeMaxDynamicSharedMemorySize,
                         LAYER_DSMEM);

    const int TB = 256;
    k_prep<<<(NN * F / 4 + TB - 1) / TB, TB>>>((const int*)ei, (const float4*)x);
    k_count<<<(NE / 4 + TB - 1) / TB, TB>>>(ei);
    k_scanA<<<NB, 128>>>();
    k_scanB<<<NB, 192>>>();
    k_fill<<<(NE / 4 + TB - 1) / TB, TB>>>(ei);

    k_layer<<<296, 128, LAYER_DSMEM>>>(W1, b1, W3, b3, out, 0);
    k_layer<<<296, 128, LAYER_DSMEM>>>(W2, b2, W3, b3, out, 1);
}

// round 10
// speedup vs baseline: 1.4603x; 1.4603x over previous
#include <cuda_runtime.h>
#include <cuda_fp16.h>

#define NN 20000
#define NE 640000
#define F  128
#define UN 16                     // nodes per tile in MLP kernel (20000 % 16 == 0)
#define NGROUPS (NN / UN)         // 1250
#define MLP_DSMEM (65536 + 16384) // Wsp pairs 64KB + duplicated input tile 16KB
#define NB 160                    // scan blocks
#define CH 125                    // elements per scan block (160*125 = 20000)

// ---------------- scratch (device globals; no allocations allowed) ----------
__device__ __align__(16) float  g_agg[NN * F];   // aggregated (mean) features, f32
__device__ __align__(16) __half g_xh[NN * F];    // x in half (gather source L1)
__device__ __align__(16) __half g_hh[NN * F];    // h1 in half (gather source L2)
__device__ float g_inv[NN];       // 1 / max(indegree, 1)
__device__ int   g_cnt[NN];       // zero at start; scanB re-zeroes each call
__device__ int   g_off[NN + 1];   // CSR offsets by dst
__device__ int   g_cur[NN];       // fill cursors
__device__ int   g_esrc[NE];      // src ids grouped by dst
__device__ int   g_bsum[NB];      // per-block count sums
__device__ int   g_tick[2];       // mlp work tickets (reset in k_prep)
__device__ int   g_is64;          // 1 if edge_index is int64, 0 if int32

// ---------------- packed f32x2 helpers ---------------------------------------
__device__ __forceinline__ unsigned long long ffma2(unsigned long long a,
                                                    unsigned long long b,
                                                    unsigned long long c) {
    unsigned long long d;
    asm("fma.rn.f32x2 %0, %1, %2, %3;" : "=l"(d) : "l"(a), "l"(b), "l"(c));
    return d;
}
__device__ __forceinline__ void unpack2(unsigned long long p, float& lo, float& hi) {
    asm("mov.b64 {%0, %1}, %2;" : "=f"(lo), "=f"(hi) : "l"(p));
}

// ---------------- prep: x->half + dtype detect + ticket reset ----------------
// int64 node ids < 2^31 have zero high words at odd int32 indices.
__global__ void k_prep(const int* __restrict__ ei32, const float4* __restrict__ x) {
    int i = blockIdx.x * blockDim.x + threadIdx.x;
    if (i < NN * F / 4) {
        float4 v = x[i];
        __half2* o = (__half2*)g_xh;
        o[2 * i + 0] = __floats2half2_rn(v.x, v.y);
        o[2 * i + 1] = __floats2half2_rn(v.z, v.w);
    }
    if (i < 2) g_tick[i] = 0;
    if (i < 32) {
        int v = 0;
#pragma unroll
        for (int j = 0; j < 4; ++j) v |= ei32[2 * (i + 32 * j) + 1];
#pragma unroll
        for (int d = 16; d; d >>= 1) v |= __shfl_xor_sync(0xffffffffu, v, d);
        if (i == 0) g_is64 = (v == 0) ? 1 : 0;
    }
}

// ---------------- CSR build: 4 edges per thread -------------------------------
__global__ void k_count(const void* __restrict__ ei) {
    int t = blockIdx.x * blockDim.x + threadIdx.x;
    if (t >= NE / 4) return;
    int d0, d1, d2, d3;
    if (g_is64) {
        const longlong2* p = (const longlong2*)ei;
        longlong2 a = p[(NE + 4 * t) / 2], b = p[(NE + 4 * t) / 2 + 1];
        d0 = (int)a.x; d1 = (int)a.y; d2 = (int)b.x; d3 = (int)b.y;
    } else {
        int4 a = ((const int4*)ei)[(NE + 4 * t) / 4];
        d0 = a.x; d1 = a.y; d2 = a.z; d3 = a.w;
    }
    if ((unsigned)d0 < NN) atomicAdd(&g_cnt[d0], 1);
    if ((unsigned)d1 < NN) atomicAdd(&g_cnt[d1], 1);
    if ((unsigned)d2 < NN) atomicAdd(&g_cnt[d2], 1);
    if ((unsigned)d3 < NN) atomicAdd(&g_cnt[d3], 1);
}

// ---------------- hierarchical scan (grid=160) --------------------------------
__global__ void __launch_bounds__(128) k_scanA() {
    int b = blockIdx.x, t = threadIdx.x, lane = t & 31, wid = t >> 5;
    __shared__ int ws[4];
    int c = (t < CH) ? g_cnt[b * CH + t] : 0;
#pragma unroll
    for (int d = 16; d; d >>= 1) c += __shfl_xor_sync(0xffffffffu, c, d);
    if (lane == 0) ws[wid] = c;
    __syncthreads();
    if (t == 0) g_bsum[b] = ws[0] + ws[1] + ws[2] + ws[3];
}

// B: block base = sum of earlier block sums; scan own chunk; re-zero g_cnt.
__global__ void __launch_bounds__(192) k_scanB() {
    int b = blockIdx.x, t = threadIdx.x, lane = t & 31, wid = t >> 5;
    __shared__ int bs[6];
    __shared__ int wsum[4];
    int v = (t < b) ? g_bsum[t] : 0;      // b <= 159 < 192 threads
#pragma unroll
    for (int d = 16; d; d >>= 1) v += __shfl_xor_sync(0xffffffffu, v, d);
    if (lane == 0) bs[wid] = v;
    __syncthreads();
    int base = bs[0] + bs[1] + bs[2] + bs[3] + bs[4] + bs[5];

    int i = b * CH + t;
    int c = (t < CH) ? g_cnt[i] : 0;
    int s = c;
#pragma unroll
    for (int d = 1; d < 32; d <<= 1) {
        int u = __shfl_up_sync(0xffffffffu, s, d);
        if (lane >= d) s += u;
    }
    if (lane == 31 && wid < 4) wsum[wid] = s;
    __syncthreads();
    int off = base;
#pragma unroll
    for (int w = 0; w < 4; ++w) off += (w < wid) ? wsum[w] : 0;
    if (t < CH) {
        int inc = off + s;
        g_off[i + 1] = inc;
        g_cur[i]     = inc - c;
        g_inv[i]     = 1.0f / (float)(c > 0 ? c : 1);
        g_cnt[i]     = 0;                  // ready for next call
    }
    if (b == 0 && t == 0) g_off[0] = 0;
}

__global__ void k_fill(const void* __restrict__ ei) {
    int t = blockIdx.x * blockDim.x + threadIdx.x;
    if (t >= NE / 4) return;
    int s0, s1, s2, s3, d0, d1, d2, d3;
    if (g_is64) {
        const longlong2* p = (const longlong2*)ei;
        longlong2 a = p[(4 * t) / 2],       b = p[(4 * t) / 2 + 1];
        longlong2 c = p[(NE + 4 * t) / 2],  d = p[(NE + 4 * t) / 2 + 1];
        s0 = (int)a.x; s1 = (int)a.y; s2 = (int)b.x; s3 = (int)b.y;
        d0 = (int)c.x; d1 = (int)c.y; d2 = (int)d.x; d3 = (int)d.y;
    } else {
        int4 a = ((const int4*)ei)[t];
        int4 c = ((const int4*)ei)[(NE + 4 * t) / 4];
        s0 = a.x; s1 = a.y; s2 = a.z; s3 = a.w;
        d0 = c.x; d1 = c.y; d2 = c.z; d3 = c.w;
    }
    if ((unsigned)d0 < NN && (unsigned)s0 < NN) g_esrc[atomicAdd(&g_cur[d0], 1)] = s0;
    if ((unsigned)d1 < NN && (unsigned)s1 < NN) g_esrc[atomicAdd(&g_cur[d1], 1)] = s1;
    if ((unsigned)d2 < NN && (unsigned)s2 < NN) g_esrc[atomicAdd(&g_cur[d2], 1)] = s2;
    if ((unsigned)d3 < NN && (unsigned)s3 < NN) g_esrc[atomicAdd(&g_cur[d3], 1)] = s3;
}

// ---------------- mean aggregation: one warp per dst node --------------------
// Gathers HALF rows (256B = 2 L2 lines per edge), accumulates f32 -> g_agg f32.
__global__ void k_agg(int use_h) {
    int warp = (blockIdx.x * blockDim.x + threadIdx.x) >> 5;
    int lane = threadIdx.x & 31;
    if (warp >= NN) return;
    const uint2* __restrict__ feat = use_h ? (const uint2*)g_hh : (const uint2*)g_xh;
    int beg = g_off[warp], end = g_off[warp + 1];
    float4 acc = make_float4(0.f, 0.f, 0.f, 0.f);
    int e0 = beg;
    for (; e0 + 32 <= end; e0 += 32) {          // full chunks, no bounds checks
        int myid = g_esrc[e0 + lane];
#pragma unroll 8
        for (int j = 0; j < 32; ++j) {
            int s = __shfl_sync(0xffffffffu, myid, j);
            uint2 r = feat[s * 32 + lane];
            float2 a = __half22float2(*(__half2*)&r.x);
            float2 b = __half22float2(*(__half2*)&r.y);
            acc.x += a.x; acc.y += a.y; acc.z += b.x; acc.w += b.y;
        }
    }
    int n = end - e0;
    if (n) {
        int myid = (lane < n) ? g_esrc[e0 + lane] : 0;
        for (int j = 0; j < n; ++j) {
            int s = __shfl_sync(0xffffffffu, myid, j);
            uint2 r = feat[s * 32 + lane];
            float2 a = __half22float2(*(__half2*)&r.x);
            float2 b = __half22float2(*(__half2*)&r.y);
            acc.x += a.x; acc.y += a.y; acc.z += b.x; acc.w += b.y;
        }
    }
    float inv = g_inv[warp];
    acc.x *= inv; acc.y *= inv; acc.z *= inv; acc.w *= inv;
    ((float4*)g_agg)[warp * 32 + lane] = acc;
}

// ---------------- (g_agg @ W + b) -> relu, packed f32x2 FMA ------------------
// Thread: jp = tid&63 owns column pair (jp, jp+64); owns 8 of the 16 tile nodes.
// layer2=0: store relu result as half to g_hh.
// layer2=1: keep h2 in registers, project 128->2 with W3 (warp reduce), write out.
// Groups claimed via atomic ticket for load balance.
__global__ void __launch_bounds__(128) k_mlp(
    const float* __restrict__ W,  const float* __restrict__ b,
    const float* __restrict__ W3, const float* __restrict__ b3,
    float* __restrict__ out, int layer2)
{
    extern __shared__ char dyn[];
    float2*             Wsp  = (float2*)dyn;                  // [k][jp] pairs, 64KB
    float4*             Insd = (float4*)(dyn + 65536);        // duplicated inputs, 16KB
    unsigned long long* InsU = (unsigned long long*)Insd;
    __shared__ float2 part[4][8];
    __shared__ int s_g;

    int tid = threadIdx.x;
    int wid = tid >> 5, lane = tid & 31;
    int jp  = tid & 63;
    int u0  = (tid >> 6) * 8;

    for (int e = tid; e < F * 64; e += 128) {
        int k = e >> 6, j = e & 63;
        Wsp[e] = make_float2(W[k * F + j], W[k * F + j + 64]);
    }
    float bj0 = b[jp], bj1 = b[jp + 64];
    float2 w3a = make_float2(0.f, 0.f), w3b = make_float2(0.f, 0.f);
    float b30 = 0.f, b31 = 0.f;
    if (layer2) {
        w3a = ((const float2*)W3)[jp];
        w3b = ((const float2*)W3)[jp + 64];
        b30 = b3[0]; b31 = b3[1];
    }
    const unsigned long long* WsU = (const unsigned long long*)Wsp;
    const float4* __restrict__ in4 = (const float4*)g_agg;

    for (;;) {
        __syncthreads();   // Wsp staged / prior Insd & part reads done
        if (tid == 0) s_g = atomicAdd(&g_tick[layer2], 1);
        __syncthreads();
        int g = s_g;
        if (g >= NGROUPS) break;
        int n0 = g * UN;

        for (int i = tid; i < UN * 32; i += 128) {
            float4 v = in4[n0 * 32 + i];           // node u=(i>>5), k4=(i&31)
            int u = i >> 5, k4 = i & 31;
            Insd[u * 64 + 2 * k4 + 0] = make_float4(v.x, v.x, v.y, v.y);
            Insd[u * 64 + 2 * k4 + 1] = make_float4(v.z, v.z, v.w, v.w);
        }
        __syncthreads();

        unsigned long long ac[8];
#pragma unroll
        for (int u = 0; u < 8; ++u) ac[u] = 0ULL;

#pragma unroll 2
        for (int k4 = 0; k4 < 32; ++k4) {
            unsigned long long w0 = WsU[(4 * k4 + 0) * 64 + jp];
            unsigned long long w1 = WsU[(4 * k4 + 1) * 64 + jp];
            unsigned long long w2 = WsU[(4 * k4 + 2) * 64 + jp];
            unsigned long long w3 = WsU[(4 * k4 + 3) * 64 + jp];
#pragma unroll
            for (int u = 0; u < 8; ++u) {
                const unsigned long long* p = &InsU[((u0 + u) * 64 + 2 * k4) * 2];
                ulonglong2 A = *(const ulonglong2*)p;        // (vx,vx) (vy,vy)
                ulonglong2 B = *(const ulonglong2*)(p + 2);  // (vz,vz) (vw,vw)
                ac[u] = ffma2(A.x, w0, ac[u]);
                ac[u] = ffma2(A.y, w1, ac[u]);
                ac[u] = ffma2(B.x, w2, ac[u]);
                ac[u] = ffma2(B.y, w3, ac[u]);
            }
        }

        if (!layer2) {
#pragma unroll
            for (int u = 0; u < 8; ++u) {
                float lo, hi;
                unpack2(ac[u], lo, hi);
                float r0 = fmaxf(lo + bj0, 0.f), r1 = fmaxf(hi + bj1, 0.f);
                int node = n0 + u0 + u;
                g_hh[node * F + jp]      = __float2half(r0);
                g_hh[node * F + jp + 64] = __float2half(r1);
            }
        } else {
#pragma unroll
            for (int u = 0; u < 8; ++u) {
                float lo, hi;
                unpack2(ac[u], lo, hi);
                float r0 = fmaxf(lo + bj0, 0.f), r1 = fmaxf(hi + bj1, 0.f);
                float o0 = r0 * w3a.x + r1 * w3b.x;
                float o1 = r0 * w3a.y + r1 * w3b.y;
#pragma unroll
                for (int d = 16; d; d >>= 1) {
                    o0 += __shfl_down_sync(0xffffffffu, o0, d);
                    o1 += __shfl_down_sync(0xffffffffu, o1, d);
                }
                if (lane == 0) part[wid][u] = make_float2(o0, o1);
            }
            __syncthreads();
            if (tid < 16) {                       // node n0+tid
                int wa = (tid < 8) ? 0 : 2;       // warps {0,1}: u0=0; {2,3}: u0=8
                int uu = tid & 7;
                float2 pa = part[wa][uu], pb = part[wa + 1][uu];
                out[(n0 + tid) * 2 + 0] = pa.x + pb.x + b30;
                out[(n0 + tid) * 2 + 1] = pa.y + pb.y + b31;
            }
        }
    }
}

// ---------------- launch -----------------------------------------------------
extern "C" void kernel_launch(void* const* d_in, const int* in_sizes, int n_in,
                              void* d_out, int out_size) {
    const float* x  = (const float*)d_in[0];
    const void*  ei = d_in[1];
    const float* W1 = (const float*)d_in[2];
    const float* b1 = (const float*)d_in[3];
    const float* W2 = (const float*)d_in[4];
    const float* b2 = (const float*)d_in[5];
    const float* W3 = (const float*)d_in[6];
    const float* b3 = (const float*)d_in[7];
    float* out = (float*)d_out;

    cudaFuncSetAttribute(k_mlp, cudaFuncAttributeMaxDynamicSharedMemorySize,
                         MLP_DSMEM);

    const int TB = 256;
    k_prep<<<(NN * F / 4 + TB - 1) / TB, TB>>>((const int*)ei, (const float4*)x);
    k_count<<<(NE / 4 + TB - 1) / TB, TB>>>(ei);
    k_scanA<<<NB, 128>>>();
    k_scanB<<<NB, 192>>>();
    k_fill<<<(NE / 4 + TB - 1) / TB, TB>>>(ei);

    int agg_blocks = (NN * 32 + TB - 1) / TB;   // one warp per node

    // layer 1
    k_agg<<<agg_blocks, TB>>>(0);
    k_mlp<<<296, 128, MLP_DSMEM>>>(W1, b1, W3, b3, out, 0);
    // layer 2 (+ fused final projection)
    k_agg<<<agg_blocks, TB>>>(1);
    k_mlp<<<296, 128, MLP_DSMEM>>>(W2, b2, W3, b3, out, 1);
}

// round 11
// speedup vs baseline: 1.6603x; 1.1369x over previous
#include <cuda_runtime.h>
#include <cuda_fp16.h>

#define NN 20000
#define NE 640000
#define F  128
#define UN 16                      // nodes per group (20000 % 16 == 0)
#define NGROUPS (NN / UN)          // 1250
#define NS 4                       // ring stages
#define STAGE_BYTES (UN * F * 8)   // 16384: 16 nodes x 128 cols x 8B dup pair
#define LAYER_DSMEM (65536 + NS * STAGE_BYTES)   // 128 KB
#define NCTA 148
#define NPROD 16                   // producer (gather) warps
#define NCONS 8                    // consumer (matmul) warps
#define NTHREADS ((NPROD + NCONS) * 32)          // 768
#define NB 160                     // scan blocks
#define CH 125                     // elements per scan block (160*125 = 20000)

// ---------------- scratch (device globals; no allocations allowed) ----------
__device__ __align__(16) __half g_xh[NN * F];    // x in half (gather source L1)
__device__ __align__(16) __half g_hh[NN * F];    // h1 in half (gather source L2)
__device__ float g_inv[NN];       // 1 / max(indegree, 1)
__device__ int   g_cnt[NN];       // zero at start; scanB re-zeroes each call
__device__ int   g_off[NN + 1];   // CSR offsets by dst
__device__ int   g_cur[NN];       // fill cursors
__device__ int   g_esrc[NE];      // src ids grouped by dst
__device__ int   g_bsum[NB];      // per-block count sums

// ---------------- packed f32x2 helpers ---------------------------------------
__device__ __forceinline__ unsigned long long ffma2(unsigned long long a,
                                                    unsigned long long b,
                                                    unsigned long long c) {
    unsigned long long d;
    asm("fma.rn.f32x2 %0, %1, %2, %3;" : "=l"(d) : "l"(a), "l"(b), "l"(c));
    return d;
}
__device__ __forceinline__ void unpack2(unsigned long long p, float& lo, float& hi) {
    asm("mov.b64 {%0, %1}, %2;" : "=f"(lo), "=f"(hi) : "l"(p));
}

// Per-block int64 detection: int64 node ids < 2^31 have zero high words at odd
// int32 indices; int32 data has uniform node ids there (P[32 zeros] ~ 0).
__device__ __forceinline__ int block_is64(const int* __restrict__ ei32,
                                          int* __restrict__ s64) {
    if (threadIdx.x < 32) {
        int v = 0;
#pragma unroll
        for (int j = 0; j < 4; ++j) v |= ei32[2 * (threadIdx.x + 32 * j) + 1];
#pragma unroll
        for (int d = 16; d; d >>= 1) v |= __shfl_xor_sync(0xffffffffu, v, d);
        if (threadIdx.x == 0) *s64 = (v == 0) ? 1 : 0;
    }
    __syncthreads();
    return *s64;
}

// ---------------- CSR build: 4 edges per thread -------------------------------
__global__ void k_count(const void* __restrict__ ei) {
    __shared__ int s64;
    int is64 = block_is64((const int*)ei, &s64);
    int t = blockIdx.x * blockDim.x + threadIdx.x;
    if (t >= NE / 4) return;
    int d0, d1, d2, d3;
    if (is64) {
        const longlong2* p = (const longlong2*)ei;
        longlong2 a = p[(NE + 4 * t) / 2], b = p[(NE + 4 * t) / 2 + 1];
        d0 = (int)a.x; d1 = (int)a.y; d2 = (int)b.x; d3 = (int)b.y;
    } else {
        int4 a = ((const int4*)ei)[(NE + 4 * t) / 4];
        d0 = a.x; d1 = a.y; d2 = a.z; d3 = a.w;
    }
    if ((unsigned)d0 < NN) atomicAdd(&g_cnt[d0], 1);
    if ((unsigned)d1 < NN) atomicAdd(&g_cnt[d1], 1);
    if ((unsigned)d2 < NN) atomicAdd(&g_cnt[d2], 1);
    if ((unsigned)d3 < NN) atomicAdd(&g_cnt[d3], 1);
}

// ---------------- hierarchical scan (grid=160) --------------------------------
__global__ void __launch_bounds__(128) k_scanA() {
    int b = blockIdx.x, t = threadIdx.x, lane = t & 31, wid = t >> 5;
    __shared__ int ws[4];
    int c = (t < CH) ? g_cnt[b * CH + t] : 0;
#pragma unroll
    for (int d = 16; d; d >>= 1) c += __shfl_xor_sync(0xffffffffu, c, d);
    if (lane == 0) ws[wid] = c;
    __syncthreads();
    if (t == 0) g_bsum[b] = ws[0] + ws[1] + ws[2] + ws[3];
}

// B: block base = sum of earlier block sums; scan own chunk; re-zero g_cnt.
__global__ void __launch_bounds__(192) k_scanB() {
    int b = blockIdx.x, t = threadIdx.x, lane = t & 31, wid = t >> 5;
    __shared__ int bs[6];
    __shared__ int wsum[4];
    int v = (t < b) ? g_bsum[t] : 0;      // b <= 159 < 192 threads
#pragma unroll
    for (int d = 16; d; d >>= 1) v += __shfl_xor_sync(0xffffffffu, v, d);
    if (lane == 0) bs[wid] = v;
    __syncthreads();
    int base = bs[0] + bs[1] + bs[2] + bs[3] + bs[4] + bs[5];

    int i = b * CH + t;
    int c = (t < CH) ? g_cnt[i] : 0;
    int s = c;
#pragma unroll
    for (int d = 1; d < 32; d <<= 1) {
        int u = __shfl_up_sync(0xffffffffu, s, d);
        if (lane >= d) s += u;
    }
    if (lane == 31 && wid < 4) wsum[wid] = s;
    __syncthreads();
    int off = base;
#pragma unroll
    for (int w = 0; w < 4; ++w) off += (w < wid) ? wsum[w] : 0;
    if (t < CH) {
        int inc = off + s;
        g_off[i + 1] = inc;
        g_cur[i]     = inc - c;
        g_inv[i]     = 1.0f / (float)(c > 0 ? c : 1);
        g_cnt[i]     = 0;                  // ready for next call
    }
    if (b == 0 && t == 0) g_off[0] = 0;
}

__global__ void k_fill(const void* __restrict__ ei) {
    __shared__ int s64;
    int is64 = block_is64((const int*)ei, &s64);
    int t = blockIdx.x * blockDim.x + threadIdx.x;
    if (t >= NE / 4) return;
    int s0, s1, s2, s3, d0, d1, d2, d3;
    if (is64) {
        const longlong2* p = (const longlong2*)ei;
        longlong2 a = p[(4 * t) / 2],       b = p[(4 * t) / 2 + 1];
        longlong2 c = p[(NE + 4 * t) / 2],  d = p[(NE + 4 * t) / 2 + 1];
        s0 = (int)a.x; s1 = (int)a.y; s2 = (int)b.x; s3 = (int)b.y;
        d0 = (int)c.x; d1 = (int)c.y; d2 = (int)d.x; d3 = (int)d.y;
    } else {
        int4 a = ((const int4*)ei)[t];
        int4 c = ((const int4*)ei)[(NE + 4 * t) / 4];
        s0 = a.x; s1 = a.y; s2 = a.z; s3 = a.w;
        d0 = c.x; d1 = c.y; d2 = c.z; d3 = c.w;
    }
    if ((unsigned)d0 < NN && (unsigned)s0 < NN) g_esrc[atomicAdd(&g_cur[d0], 1)] = s0;
    if ((unsigned)d1 < NN && (unsigned)s1 < NN) g_esrc[atomicAdd(&g_cur[d1], 1)] = s1;
    if ((unsigned)d2 < NN && (unsigned)s2 < NN) g_esrc[atomicAdd(&g_cur[d2], 1)] = s2;
    if ((unsigned)d3 < NN && (unsigned)s3 < NN) g_esrc[atomicAdd(&g_cur[d3], 1)] = s3;
}

// ---------------- convert x -> half ------------------------------------------
__global__ void k_tohalf(const float4* __restrict__ x) {
    int i = blockIdx.x * blockDim.x + threadIdx.x;   // one float4 -> 2x half2
    if (i < NN * F / 4) {
        float4 v = x[i];
        __half2* o = (__half2*)g_xh;
        o[2 * i + 0] = __floats2half2_rn(v.x, v.y);
        o[2 * i + 1] = __floats2half2_rn(v.z, v.w);
    }
}

// ---------------- warp-specialized fused layer --------------------------------
// 1 CTA/SM, 24 warps: 16 producers gather+mean one node each per group and
// write duplicated (v,v) pairs into a 4-stage smem ring; 8 consumers run the
// packed-f32x2 matmul from the ring. layer2=1 additionally projects 128->2.
__global__ void __launch_bounds__(NTHREADS, 1) k_layer(
    const float* __restrict__ W,  const float* __restrict__ b,
    const float* __restrict__ W3, const float* __restrict__ b3,
    float* __restrict__ out, int layer2)
{
    extern __shared__ char dyn[];
    float2* Wsp = (float2*)dyn;                      // [k][jp] pairs, 64KB
    __shared__ int ready[NS];                        // nodes written per stage (monotone)
    __shared__ int freed[NS];                        // groups consumed per stage (monotone)
    __shared__ float2 part[NCONS][4];

    int tid = threadIdx.x;
    int wid = tid >> 5, lane = tid & 31;
    int cta = blockIdx.x;

    if (tid < NS) { ready[tid] = 0; freed[tid] = 0; }
    for (int e = tid; e < F * 64; e += NTHREADS) {
        int k = e >> 6, j = e & 63;
        Wsp[e] = make_float2(W[k * F + j], W[k * F + j + 64]);
    }
    __syncthreads();            // last block-wide barrier; roles diverge below

    if (wid < NPROD) {
        // ---------------- producer: gather + mean node (g*16 + wid) ----------
        const uint2* __restrict__ feat = layer2 ? (const uint2*)g_hh
                                                : (const uint2*)g_xh;
        int lg = 0;
        for (int g = cta; g < NGROUPS; g += NCTA, ++lg) {
            int s = lg & (NS - 1);
            int c = lg >> 2;                          // lg / NS
            while (((volatile int*)freed)[s] < c) __nanosleep(50);

            int node = g * UN + wid;
            int beg = g_off[node], end = g_off[node + 1];
            float4 acc = make_float4(0.f, 0.f, 0.f, 0.f);
            int e0 = beg;
            for (; e0 + 32 <= end; e0 += 32) {
                int myid = g_esrc[e0 + lane];
#pragma unroll 8
                for (int j = 0; j < 32; ++j) {
                    int sid = __shfl_sync(0xffffffffu, myid, j);
                    uint2 r = feat[sid * 32 + lane];
                    float2 a = __half22float2(*(__half2*)&r.x);
                    float2 bb = __half22float2(*(__half2*)&r.y);
                    acc.x += a.x; acc.y += a.y; acc.z += bb.x; acc.w += bb.y;
                }
            }
            int n = end - e0;
            if (n) {
                int myid = (lane < n) ? g_esrc[e0 + lane] : 0;
                for (int j = 0; j < n; ++j) {
                    int sid = __shfl_sync(0xffffffffu, myid, j);
                    uint2 r = feat[sid * 32 + lane];
                    float2 a = __half22float2(*(__half2*)&r.x);
                    float2 bb = __half22float2(*(__half2*)&r.y);
                    acc.x += a.x; acc.y += a.y; acc.z += bb.x; acc.w += bb.y;
                }
            }
            float inv = g_inv[node];
            float4* Insd = (float4*)(dyn + 65536 + s * STAGE_BYTES);
            Insd[wid * 64 + 2 * lane]     = make_float4(acc.x * inv, acc.x * inv,
                                                        acc.y * inv, acc.y * inv);
            Insd[wid * 64 + 2 * lane + 1] = make_float4(acc.z * inv, acc.z * inv,
                                                        acc.w * inv, acc.w * inv);
            __threadfence_block();
            if (lane == 0) atomicAdd(&ready[s], 1);
        }
    } else {
        // ---------------- consumer: matmul from ring -------------------------
        int ctid = tid - NPROD * 32;                  // 0..255
        int jp   = ctid & 63;                         // column pair (jp, jp+64)
        int un0  = (ctid >> 6) * 4;                   // 4 nodes of the 16
        int cw   = ctid >> 5;                         // consumer warp 0..7
        float bj0 = b[jp], bj1 = b[jp + 64];
        float2 w3a = make_float2(0.f, 0.f), w3b = make_float2(0.f, 0.f);
        float b30 = 0.f, b31 = 0.f;
        if (layer2) {
            w3a = ((const float2*)W3)[jp];
            w3b = ((const float2*)W3)[jp + 64];
            b30 = b3[0]; b31 = b3[1];
        }
        const unsigned long long* WsU = (const unsigned long long*)Wsp;

        int lg = 0;
        for (int g = cta; g < NGROUPS; g += NCTA, ++lg) {
            int s = lg & (NS - 1);
            int c = lg >> 2;
            int target = UN * (c + 1);
            while (((volatile int*)ready)[s] < target) __nanosleep(50);
            __threadfence_block();

            const unsigned long long* InsU =
                (const unsigned long long*)(dyn + 65536 + s * STAGE_BYTES);
            unsigned long long ac[4] = {0ULL, 0ULL, 0ULL, 0ULL};
#pragma unroll 4
            for (int k4 = 0; k4 < 32; ++k4) {
                unsigned long long w0 = WsU[(4 * k4 + 0) * 64 + jp];
                unsigned long long w1 = WsU[(4 * k4 + 1) * 64 + jp];
                unsigned long long w2 = WsU[(4 * k4 + 2) * 64 + jp];
                unsigned long long w3 = WsU[(4 * k4 + 3) * 64 + jp];
#pragma unroll
                for (int u = 0; u < 4; ++u) {
                    const unsigned long long* p =
                        &InsU[((un0 + u) * 64 + 2 * k4) * 2];
                    ulonglong2 A = *(const ulonglong2*)p;        // (vx,vx)(vy,vy)
                    ulonglong2 B = *(const ulonglong2*)(p + 2);  // (vz,vz)(vw,vw)
                    ac[u] = ffma2(A.x, w0, ac[u]);
                    ac[u] = ffma2(A.y, w1, ac[u]);
                    ac[u] = ffma2(B.x, w2, ac[u]);
                    ac[u] = ffma2(B.y, w3, ac[u]);
                }
            }

            int n0 = g * UN;
            if (!layer2) {
#pragma unroll
                for (int u = 0; u < 4; ++u) {
                    float lo, hi;
                    unpack2(ac[u], lo, hi);
                    float r0 = fmaxf(lo + bj0, 0.f), r1 = fmaxf(hi + bj1, 0.f);
                    int node = n0 + un0 + u;
                    g_hh[node * F + jp]      = __float2half(r0);
                    g_hh[node * F + jp + 64] = __float2half(r1);
                }
                asm volatile("bar.sync 1, %0;" :: "n"(NCONS * 32) : "memory");
                if (ctid == 0) atomicAdd(&freed[s], 1);
            } else {
#pragma unroll
                for (int u = 0; u < 4; ++u) {
                    float lo, hi;
                    unpack2(ac[u], lo, hi);
                    float r0 = fmaxf(lo + bj0, 0.f), r1 = fmaxf(hi + bj1, 0.f);
                    float o0 = r0 * w3a.x + r1 * w3b.x;
                    float o1 = r0 * w3a.y + r1 * w3b.y;
#pragma unroll
                    for (int d = 16; d; d >>= 1) {
                        o0 += __shfl_down_sync(0xffffffffu, o0, d);
                        o1 += __shfl_down_sync(0xffffffffu, o1, d);
                    }
                    if (lane == 0) part[cw][u] = make_float2(o0, o1);
                }
                asm volatile("bar.sync 1, %0;" :: "n"(NCONS * 32) : "memory");
                if (ctid == 0) atomicAdd(&freed[s], 1);
                if (ctid < 16) {                      // node n0 + ctid
                    int wp = ctid >> 2, uu = ctid & 3;
                    float2 pa = part[2 * wp][uu], pb = part[2 * wp + 1][uu];
                    out[(n0 + ctid) * 2 + 0] = pa.x + pb.x + b30;
                    out[(n0 + ctid) * 2 + 1] = pa.y + pb.y + b31;
                }
                asm volatile("bar.sync 1, %0;" :: "n"(NCONS * 32) : "memory");
            }
        }
    }
}

// ---------------- launch -----------------------------------------------------
extern "C" void kernel_launch(void* const* d_in, const int* in_sizes, int n_in,
                              void* d_out, int out_size) {
    const float* x  = (const float*)d_in[0];
    const void*  ei = d_in[1];
    const float* W1 = (const float*)d_in[2];
    const float* b1 = (const float*)d_in[3];
    const float* W2 = (const float*)d_in[4];
    const float* b2 = (const float*)d_in[5];
    const float* W3 = (const float*)d_in[6];
    const float* b3 = (const float*)d_in[7];
    float* out = (float*)d_out;

    cudaFuncSetAttribute(k_layer, cudaFuncAttributeMaxDynamicSharedMemorySize,
                         LAYER_DSMEM);

    const int TB = 256;
    k_count<<<(NE / 4 + TB - 1) / TB, TB>>>(ei);
    k_scanA<<<NB, 128>>>();
    k_scanB<<<NB, 192>>>();
    k_fill<<<(NE / 4 + TB - 1) / TB, TB>>>(ei);          // profiled slot 4
    k_tohalf<<<(NN * F / 4 + TB - 1) / TB, TB>>>((const float4*)x);

    k_layer<<<NCTA, NTHREADS, LAYER_DSMEM>>>(W1, b1, W3, b3, out, 0);
    k_layer<<<NCTA, NTHREADS, LAYER_DSMEM>>>(W2, b2, W3, b3, out, 1);
}

// round 12
// speedup vs baseline: 1.7473x; 1.0524x over previous
#include <cuda_runtime.h>
#include <cuda_fp16.h>

#define NN 20000
#define NE 640000
#define F  128
#define UN 16                      // nodes per group (20000 % 16 == 0)
#define NGROUPS (NN / UN)          // 1250
#define NS 4                       // ring stages
#define STAGE_BYTES (UN * F * 8)   // 16384: 16 nodes x 128 cols x 8B dup pair
#define LAYER_DSMEM (65536 + NS * STAGE_BYTES)   // 128 KB
#define NCTA 148
#define NPROD 16                   // producer (gather) warps
#define NCONS 8                    // consumer (matmul) warps
#define NTHREADS ((NPROD + NCONS) * 32)          // 768
#define NB 160                     // scan blocks
#define CH 125                     // elements per scan block (160*125 = 20000)

// ---------------- scratch (device globals; no allocations allowed) ----------
__device__ __align__(16) __half g_xh[NN * F];    // x in half (gather source L1)
__device__ __align__(16) __half g_hh[NN * F];    // h1 in half (gather source L2)
__device__ float g_inv[NN];       // 1 / max(indegree, 1)
__device__ int   g_cnt[NN];       // zero at start; scanB re-zeroes each call
__device__ int   g_off[NN + 1];   // CSR offsets by dst
__device__ __align__(16) int g_tkt[NE];   // per-edge ticket within its dst segment
__device__ int   g_esrc[NE];      // src ids grouped by dst
__device__ int   g_bsum[NB];      // per-block count sums

// ---------------- packed f32x2 helpers ---------------------------------------
__device__ __forceinline__ unsigned long long ffma2(unsigned long long a,
                                                    unsigned long long b,
                                                    unsigned long long c) {
    unsigned long long d;
    asm("fma.rn.f32x2 %0, %1, %2, %3;" : "=l"(d) : "l"(a), "l"(b), "l"(c));
    return d;
}
__device__ __forceinline__ void unpack2(unsigned long long p, float& lo, float& hi) {
    asm("mov.b64 {%0, %1}, %2;" : "=f"(lo), "=f"(hi) : "l"(p));
}

// Per-block int64 detection: int64 node ids < 2^31 have zero high words at odd
// int32 indices; int32 data has uniform node ids there (P[32 zeros] ~ 0).
__device__ __forceinline__ int block_is64(const int* __restrict__ ei32,
                                          int* __restrict__ s64) {
    if (threadIdx.x < 32) {
        int v = 0;
#pragma unroll
        for (int j = 0; j < 4; ++j) v |= ei32[2 * (threadIdx.x + 32 * j) + 1];
#pragma unroll
        for (int d = 16; d; d >>= 1) v |= __shfl_xor_sync(0xffffffffu, v, d);
        if (threadIdx.x == 0) *s64 = (v == 0) ? 1 : 0;
    }
    __syncthreads();
    return *s64;
}

// ---------------- prep: x->half + count with saved tickets --------------------
// grid 2500x256 = 640000 threads: thread i converts float4 i of x AND counts
// edge i (saving its ticket for the atomic-free fill).
__global__ void k_prep(const void* __restrict__ ei, const float4* __restrict__ x) {
    __shared__ int s64;
    int is64 = block_is64((const int*)ei, &s64);
    int i = blockIdx.x * blockDim.x + threadIdx.x;   // < 640000 exactly
    float4 v = x[i];
    __half2* o = (__half2*)g_xh;
    o[2 * i + 0] = __floats2half2_rn(v.x, v.y);
    o[2 * i + 1] = __floats2half2_rn(v.z, v.w);

    int dst = is64 ? (int)((const long long*)ei)[NE + i]
                   : ((const int*)ei)[NE + i];
    if ((unsigned)dst < NN) g_tkt[i] = atomicAdd(&g_cnt[dst], 1);
}

// ---------------- hierarchical scan (grid=160) --------------------------------
__global__ void __launch_bounds__(128) k_scanA() {
    int b = blockIdx.x, t = threadIdx.x, lane = t & 31, wid = t >> 5;
    __shared__ int ws[4];
    int c = (t < CH) ? g_cnt[b * CH + t] : 0;
#pragma unroll
    for (int d = 16; d; d >>= 1) c += __shfl_xor_sync(0xffffffffu, c, d);
    if (lane == 0) ws[wid] = c;
    __syncthreads();
    if (t == 0) g_bsum[b] = ws[0] + ws[1] + ws[2] + ws[3];
}

// B: block base = sum of earlier block sums; scan own chunk; re-zero g_cnt.
__global__ void __launch_bounds__(192) k_scanB() {
    int b = blockIdx.x, t = threadIdx.x, lane = t & 31, wid = t >> 5;
    __shared__ int bs[6];
    __shared__ int wsum[4];
    int v = (t < b) ? g_bsum[t] : 0;      // b <= 159 < 192 threads
#pragma unroll
    for (int d = 16; d; d >>= 1) v += __shfl_xor_sync(0xffffffffu, v, d);
    if (lane == 0) bs[wid] = v;
    __syncthreads();
    int base = bs[0] + bs[1] + bs[2] + bs[3] + bs[4] + bs[5];

    int i = b * CH + t;
    int c = (t < CH) ? g_cnt[i] : 0;
    int s = c;
#pragma unroll
    for (int d = 1; d < 32; d <<= 1) {
        int u = __shfl_up_sync(0xffffffffu, s, d);
        if (lane >= d) s += u;
    }
    if (lane == 31 && wid < 4) wsum[wid] = s;
    __syncthreads();
    int off = base;
#pragma unroll
    for (int w = 0; w < 4; ++w) off += (w < wid) ? wsum[w] : 0;
    if (t < CH) {
        int inc = off + s;
        g_off[i + 1] = inc;
        g_inv[i]     = 1.0f / (float)(c > 0 ? c : 1);
        g_cnt[i]     = 0;                  // ready for next call
    }
    if (b == 0 && t == 0) g_off[0] = 0;
}

// ---------------- fill: atomic-free, 8 edges per thread -----------------------
__global__ void k_fill(const void* __restrict__ ei) {
    __shared__ int s64;
    int is64 = block_is64((const int*)ei, &s64);
    int t = blockIdx.x * blockDim.x + threadIdx.x;
    if (t >= NE / 8) return;
    int e0 = t * 8;
    int s[8], d[8], tk[8];
    if (is64) {
        const longlong2* p = (const longlong2*)ei;
#pragma unroll
        for (int j = 0; j < 4; ++j) {
            longlong2 a = p[(e0 + 2 * j) / 2];
            s[2 * j] = (int)a.x; s[2 * j + 1] = (int)a.y;
        }
#pragma unroll
        for (int j = 0; j < 4; ++j) {
            longlong2 a = p[(NE + e0 + 2 * j) / 2];
            d[2 * j] = (int)a.x; d[2 * j + 1] = (int)a.y;
        }
    } else {
        const int4* p = (const int4*)ei;
        int4 a = p[e0 / 4], b = p[e0 / 4 + 1];
        s[0] = a.x; s[1] = a.y; s[2] = a.z; s[3] = a.w;
        s[4] = b.x; s[5] = b.y; s[6] = b.z; s[7] = b.w;
        int4 c = p[(NE + e0) / 4], e = p[(NE + e0) / 4 + 1];
        d[0] = c.x; d[1] = c.y; d[2] = c.z; d[3] = c.w;
        d[4] = e.x; d[5] = e.y; d[6] = e.z; d[7] = e.w;
    }
    {
        const int4* p = (const int4*)g_tkt;
        int4 a = p[e0 / 4], b = p[e0 / 4 + 1];
        tk[0] = a.x; tk[1] = a.y; tk[2] = a.z; tk[3] = a.w;
        tk[4] = b.x; tk[5] = b.y; tk[6] = b.z; tk[7] = b.w;
    }
    int base[8];
#pragma unroll
    for (int j = 0; j < 8; ++j)
        base[j] = ((unsigned)d[j] < NN) ? g_off[d[j]] : -1;
#pragma unroll
    for (int j = 0; j < 8; ++j)
        if (base[j] >= 0 && (unsigned)s[j] < NN)
            g_esrc[base[j] + tk[j]] = s[j];
}

// ---------------- warp-specialized fused layer --------------------------------
// 1 CTA/SM, 24 warps: 16 producers gather+mean one node each per group and
// write duplicated (v,v) pairs into a 4-stage smem ring; 8 consumers run the
// packed-f32x2 matmul from the ring. layer2=1 additionally projects 128->2.
__global__ void __launch_bounds__(NTHREADS, 1) k_layer(
    const float* __restrict__ W,  const float* __restrict__ b,
    const float* __restrict__ W3, const float* __restrict__ b3,
    float* __restrict__ out, int layer2)
{
    extern __shared__ char dyn[];
    float2* Wsp = (float2*)dyn;                      // [k][jp] pairs, 64KB
    __shared__ int ready[NS];                        // nodes written per stage (monotone)
    __shared__ int freed[NS];                        // groups consumed per stage (monotone)
    __shared__ float2 part[NCONS][4];

    int tid = threadIdx.x;
    int wid = tid >> 5, lane = tid & 31;
    int cta = blockIdx.x;

    if (tid < NS) { ready[tid] = 0; freed[tid] = 0; }
    for (int e = tid; e < F * 64; e += NTHREADS) {
        int k = e >> 6, j = e & 63;
        Wsp[e] = make_float2(W[k * F + j], W[k * F + j + 64]);
    }
    __syncthreads();            // last block-wide barrier; roles diverge below

    if (wid < NPROD) {
        // ---------------- producer: gather + mean node (g*16 + wid) ----------
        const uint2* __restrict__ feat = layer2 ? (const uint2*)g_hh
                                                : (const uint2*)g_xh;
        int lg = 0;
        for (int g = cta; g < NGROUPS; g += NCTA, ++lg) {
            int s = lg & (NS - 1);
            int c = lg >> 2;                          // lg / NS
            while (((volatile int*)freed)[s] < c) __nanosleep(50);

            int node = g * UN + wid;
            int beg = g_off[node], end = g_off[node + 1];
            float4 acc = make_float4(0.f, 0.f, 0.f, 0.f);
            int e0 = beg;
            for (; e0 + 32 <= end; e0 += 32) {
                int myid = g_esrc[e0 + lane];
#pragma unroll 8
                for (int j = 0; j < 32; ++j) {
                    int sid = __shfl_sync(0xffffffffu, myid, j);
                    uint2 r = feat[sid * 32 + lane];
                    float2 a = __half22float2(*(__half2*)&r.x);
                    float2 bb = __half22float2(*(__half2*)&r.y);
                    acc.x += a.x; acc.y += a.y; acc.z += bb.x; acc.w += bb.y;
                }
            }
            int n = end - e0;
            if (n) {
                int myid = (lane < n) ? g_esrc[e0 + lane] : 0;
                for (int j = 0; j < n; ++j) {
                    int sid = __shfl_sync(0xffffffffu, myid, j);
                    uint2 r = feat[sid * 32 + lane];
                    float2 a = __half22float2(*(__half2*)&r.x);
                    float2 bb = __half22float2(*(__half2*)&r.y);
                    acc.x += a.x; acc.y += a.y; acc.z += bb.x; acc.w += bb.y;
                }
            }
            float inv = g_inv[node];
            float4* Insd = (float4*)(dyn + 65536 + s * STAGE_BYTES);
            Insd[wid * 64 + 2 * lane]     = make_float4(acc.x * inv, acc.x * inv,
                                                        acc.y * inv, acc.y * inv);
            Insd[wid * 64 + 2 * lane + 1] = make_float4(acc.z * inv, acc.z * inv,
                                                        acc.w * inv, acc.w * inv);
            __threadfence_block();
            if (lane == 0) atomicAdd(&ready[s], 1);
        }
    } else {
        // ---------------- consumer: matmul from ring -------------------------
        int ctid = tid - NPROD * 32;                  // 0..255
        int jp   = ctid & 63;                         // column pair (jp, jp+64)
        int un0  = (ctid >> 6) * 4;                   // 4 nodes of the 16
        int cw   = ctid >> 5;                         // consumer warp 0..7
        float bj0 = b[jp], bj1 = b[jp + 64];
        float2 w3a = make_float2(0.f, 0.f), w3b = make_float2(0.f, 0.f);
        float b30 = 0.f, b31 = 0.f;
        if (layer2) {
            w3a = ((const float2*)W3)[jp];
            w3b = ((const float2*)W3)[jp + 64];
            b30 = b3[0]; b31 = b3[1];
        }
        const unsigned long long* WsU = (const unsigned long long*)Wsp;

        int lg = 0;
        for (int g = cta; g < NGROUPS; g += NCTA, ++lg) {
            int s = lg & (NS - 1);
            int c = lg >> 2;
            int target = UN * (c + 1);
            while (((volatile int*)ready)[s] < target) __nanosleep(50);
            __threadfence_block();

            const unsigned long long* InsU =
                (const unsigned long long*)(dyn + 65536 + s * STAGE_BYTES);
            unsigned long long ac[4] = {0ULL, 0ULL, 0ULL, 0ULL};
#pragma unroll 4
            for (int k4 = 0; k4 < 32; ++k4) {
                unsigned long long w0 = WsU[(4 * k4 + 0) * 64 + jp];
                unsigned long long w1 = WsU[(4 * k4 + 1) * 64 + jp];
                unsigned long long w2 = WsU[(4 * k4 + 2) * 64 + jp];
                unsigned long long w3 = WsU[(4 * k4 + 3) * 64 + jp];
#pragma unroll
                for (int u = 0; u < 4; ++u) {
                    const unsigned long long* p =
                        &InsU[((un0 + u) * 64 + 2 * k4) * 2];
                    ulonglong2 A = *(const ulonglong2*)p;        // (vx,vx)(vy,vy)
                    ulonglong2 B = *(const ulonglong2*)(p + 2);  // (vz,vz)(vw,vw)
                    ac[u] = ffma2(A.x, w0, ac[u]);
                    ac[u] = ffma2(A.y, w1, ac[u]);
                    ac[u] = ffma2(B.x, w2, ac[u]);
                    ac[u] = ffma2(B.y, w3, ac[u]);
                }
            }

            int n0 = g * UN;
            if (!layer2) {
#pragma unroll
                for (int u = 0; u < 4; ++u) {
                    float lo, hi;
                    unpack2(ac[u], lo, hi);
                    float r0 = fmaxf(lo + bj0, 0.f), r1 = fmaxf(hi + bj1, 0.f);
                    int node = n0 + un0 + u;
                    g_hh[node * F + jp]      = __float2half(r0);
                    g_hh[node * F + jp + 64] = __float2half(r1);
                }
                asm volatile("bar.sync 1, %0;" :: "n"(NCONS * 32) : "memory");
                if (ctid == 0) atomicAdd(&freed[s], 1);
            } else {
#pragma unroll
                for (int u = 0; u < 4; ++u) {
                    float lo, hi;
                    unpack2(ac[u], lo, hi);
                    float r0 = fmaxf(lo + bj0, 0.f), r1 = fmaxf(hi + bj1, 0.f);
                    float o0 = r0 * w3a.x + r1 * w3b.x;
                    float o1 = r0 * w3a.y + r1 * w3b.y;
#pragma unroll
                    for (int d = 16; d; d >>= 1) {
                        o0 += __shfl_down_sync(0xffffffffu, o0, d);
                        o1 += __shfl_down_sync(0xffffffffu, o1, d);
                    }
                    if (lane == 0) part[cw][u] = make_float2(o0, o1);
                }
                asm volatile("bar.sync 1, %0;" :: "n"(NCONS * 32) : "memory");
                if (ctid == 0) atomicAdd(&freed[s], 1);
                if (ctid < 16) {                      // node n0 + ctid
                    int wp = ctid >> 2, uu = ctid & 3;
                    float2 pa = part[2 * wp][uu], pb = part[2 * wp + 1][uu];
                    out[(n0 + ctid) * 2 + 0] = pa.x + pb.x + b30;
                    out[(n0 + ctid) * 2 + 1] = pa.y + pb.y + b31;
                }
                asm volatile("bar.sync 1, %0;" :: "n"(NCONS * 32) : "memory");
            }
        }
    }
}

// ---------------- launch -----------------------------------------------------
extern "C" void kernel_launch(void* const* d_in, const int* in_sizes, int n_in,
                              void* d_out, int out_size) {
    const float* x  = (const float*)d_in[0];
    const void*  ei = d_in[1];
    const float* W1 = (const float*)d_in[2];
    const float* b1 = (const float*)d_in[3];
    const float* W2 = (const float*)d_in[4];
    const float* b2 = (const float*)d_in[5];
    const float* W3 = (const float*)d_in[6];
    const float* b3 = (const float*)d_in[7];
    float* out = (float*)d_out;

    cudaFuncSetAttribute(k_layer, cudaFuncAttributeMaxDynamicSharedMemorySize,
                         LAYER_DSMEM);

    const int TB = 256;
    k_prep<<<NN * F / 4 / TB, TB>>>(ei, (const float4*)x);   // 2500 blocks
    k_scanA<<<NB, 128>>>();
    k_scanB<<<NB, 192>>>();
    k_fill<<<(NE / 8 + TB - 1) / TB, TB>>>(ei);              // profiled slot 4
    k_layer<<<NCTA, NTHREADS, LAYER_DSMEM>>>(W1, b1, W3, b3, out, 0);
    k_layer<<<NCTA, NTHREADS, LAYER_DSMEM>>>(W2, b2, W3, b3, out, 1);
}

// round 16
// speedup vs baseline: 2.0176x; 1.1547x over previous
#include <cuda_runtime.h>
#include <cuda_fp16.h>
#include <mma.h>
#include <cstdint>

#define NN 20000
#define NE 640000
#define F  128
#define NB 160                    // scan blocks
#define CH 125                    // elements per scan block (160*125 = 20000)

#define TILE_M   128
#define NTILES   157              // ceil(20000/128)
#define TW       20               // warps in k_tile
#define TTH      (TW * 32)        // 640 threads
#define LDA      136              // padded f16 leading dims (17*8)
#define LDB      136
#define LDC      132              // padded f32 leading dim (33*4)
// smem layout
#define SM_BIAS  0                // 128 f32
#define SM_W3    1024             // 128 float2
#define SM_A     2048             // 128x136 f16 = 34816 B
#define SM_B     36864            // 128x136 f16 = 34816 B
#define SM_C     2048             // f32 C overlays A/B after MMA (67584 B)
#define TILE_DSMEM 71680

// ---------------- scratch (device globals; no allocations allowed) ----------
__device__ __align__(16) __half g_xh[NN * F];    // x in f16 (gather source L1)
__device__ __align__(16) __half g_hh[NN * F];    // h1 in f16 (gather source L2)
__device__ float g_inv[NN];       // 1 / max(indegree, 1)
__device__ int   g_cnt[NN];       // zero at start; scanB re-zeroes each call
__device__ int   g_off[NN + 1];   // CSR offsets by dst
__device__ __align__(16) int g_tkt[NE];   // per-edge ticket within its dst segment
__device__ int   g_esrc[NE];      // src ids grouped by dst
__device__ int   g_bsum[NB];      // per-block count sums

// Per-block int64 detection: int64 node ids < 2^31 have zero high words at odd
// int32 indices; int32 data has uniform node ids there.
__device__ __forceinline__ int block_is64(const int* __restrict__ ei32,
                                          int* __restrict__ s64) {
    if (threadIdx.x < 32) {
        int v = 0;
#pragma unroll
        for (int j = 0; j < 4; ++j) v |= ei32[2 * (threadIdx.x + 32 * j) + 1];
#pragma unroll
        for (int d = 16; d; d >>= 1) v |= __shfl_xor_sync(0xffffffffu, v, d);
        if (threadIdx.x == 0) *s64 = (v == 0) ? 1 : 0;
    }
    __syncthreads();
    return *s64;
}

// ---------------- prep: x->f16 + count with saved tickets --------------------
__global__ void k_prep(const void* __restrict__ ei, const float4* __restrict__ x) {
    __shared__ int s64;
    int is64 = block_is64((const int*)ei, &s64);
    int i = blockIdx.x * blockDim.x + threadIdx.x;   // < 640000 exactly
    float4 v = x[i];
    __half2* o = (__half2*)g_xh;
    o[2 * i + 0] = __floats2half2_rn(v.x, v.y);
    o[2 * i + 1] = __floats2half2_rn(v.z, v.w);

    int dst = is64 ? (int)((const long long*)ei)[NE + i]
                   : ((const int*)ei)[NE + i];
    if ((unsigned)dst < NN) g_tkt[i] = atomicAdd(&g_cnt[dst], 1);
}

// ---------------- hierarchical scan (grid=160) --------------------------------
__global__ void __launch_bounds__(128) k_scanA() {
    int b = blockIdx.x, t = threadIdx.x, lane = t & 31, wid = t >> 5;
    __shared__ int ws[4];
    int c = (t < CH) ? g_cnt[b * CH + t] : 0;
#pragma unroll
    for (int d = 16; d; d >>= 1) c += __shfl_xor_sync(0xffffffffu, c, d);
    if (lane == 0) ws[wid] = c;
    __syncthreads();
    if (t == 0) g_bsum[b] = ws[0] + ws[1] + ws[2] + ws[3];
}

__global__ void __launch_bounds__(192) k_scanB() {
    int b = blockIdx.x, t = threadIdx.x, lane = t & 31, wid = t >> 5;
    __shared__ int bs[6];
    __shared__ int wsum[4];
    int v = (t < b) ? g_bsum[t] : 0;
#pragma unroll
    for (int d = 16; d; d >>= 1) v += __shfl_xor_sync(0xffffffffu, v, d);
    if (lane == 0) bs[wid] = v;
    __syncthreads();
    int base = bs[0] + bs[1] + bs[2] + bs[3] + bs[4] + bs[5];

    int i = b * CH + t;
    int c = (t < CH) ? g_cnt[i] : 0;
    int s = c;
#pragma unroll
    for (int d = 1; d < 32; d <<= 1) {
        int u = __shfl_up_sync(0xffffffffu, s, d);
        if (lane >= d) s += u;
    }
    if (lane == 31 && wid < 4) wsum[wid] = s;
    __syncthreads();
    int off = base;
#pragma unroll
    for (int w = 0; w < 4; ++w) off += (w < wid) ? wsum[w] : 0;
    if (t < CH) {
        int inc = off + s;
        g_off[i + 1] = inc;
        g_inv[i]     = 1.0f / (float)(c > 0 ? c : 1);
        g_cnt[i]     = 0;
    }
    if (b == 0 && t == 0) g_off[0] = 0;
}

// ---------------- fill: atomic-free, 8 edges per thread -----------------------
__global__ void k_fill(const void* __restrict__ ei) {
    __shared__ int s64;
    int is64 = block_is64((const int*)ei, &s64);
    int t = blockIdx.x * blockDim.x + threadIdx.x;
    if (t >= NE / 8) return;
    int e0 = t * 8;
    int s[8], d[8], tk[8];
    if (is64) {
        const longlong2* p = (const longlong2*)ei;
#pragma unroll
        for (int j = 0; j < 4; ++j) {
            longlong2 a = p[(e0 + 2 * j) / 2];
            s[2 * j] = (int)a.x; s[2 * j + 1] = (int)a.y;
        }
#pragma unroll
        for (int j = 0; j < 4; ++j) {
            longlong2 a = p[(NE + e0 + 2 * j) / 2];
            d[2 * j] = (int)a.x; d[2 * j + 1] = (int)a.y;
        }
    } else {
        const int4* p = (const int4*)ei;
        int4 a = p[e0 / 4], b = p[e0 / 4 + 1];
        s[0] = a.x; s[1] = a.y; s[2] = a.z; s[3] = a.w;
        s[4] = b.x; s[5] = b.y; s[6] = b.z; s[7] = b.w;
        int4 c = p[(NE + e0) / 4], e = p[(NE + e0) / 4 + 1];
        d[0] = c.x; d[1] = c.y; d[2] = c.z; d[3] = c.w;
        d[4] = e.x; d[5] = e.y; d[6] = e.z; d[7] = e.w;
    }
    {
        const int4* p = (const int4*)g_tkt;
        int4 a = p[e0 / 4], b = p[e0 / 4 + 1];
        tk[0] = a.x; tk[1] = a.y; tk[2] = a.z; tk[3] = a.w;
        tk[4] = b.x; tk[5] = b.y; tk[6] = b.z; tk[7] = b.w;
    }
    int base[8];
#pragma unroll
    for (int j = 0; j < 8; ++j)
        base[j] = ((unsigned)d[j] < NN) ? g_off[d[j]] : -1;
#pragma unroll
    for (int j = 0; j < 8; ++j)
        if (base[j] >= 0 && (unsigned)s[j] < NN)
            g_esrc[base[j] + tk[j]] = s[j];
}

// ---------------- tile layer: gather -> wmma (HMMA) -> epilogue ---------------
// Grid NTILES, 640 threads, 2 CTAs/SM (all tiles resident in one wave).
// P1: all 20 warps gather+mean f16 rows into A [128][LDA].
// P2: warps 0-15 compute 32x32 output blocks via wmma f16->f32; C overlays A/B.
// P3: epilogue; layer1: bias+relu -> f16 g_hh; layer2: +W3 projection -> out.
__global__ void __launch_bounds__(TTH, 2) k_tile(
    const float* __restrict__ W,  const float* __restrict__ bias,
    const float* __restrict__ W3, const float* __restrict__ b3,
    float* __restrict__ out, int layer2)
{
    using namespace nvcuda;
    extern __shared__ char smem[];
    int tid = threadIdx.x, wid = tid >> 5, lane = tid & 31;
    int n0 = blockIdx.x * TILE_M;

    float*  biasS = (float*)(smem + SM_BIAS);
    float2* w3S   = (float2*)(smem + SM_W3);
    __half* As    = (__half*)(smem + SM_A);
    __half* Bs    = (__half*)(smem + SM_B);
    float*  Cs    = (float*)(smem + SM_C);

    // ---- P0: stage bias / W3 / B = W (f16, row-major [k][j]) -----------------
    if (tid < 128) biasS[tid] = bias[tid];
    if (layer2 && tid < 128) w3S[tid] = ((const float2*)W3)[tid];
    for (int i = tid; i < F * F; i += TTH) {
        int k = i >> 7, j = i & 127;
        Bs[k * LDB + j] = __float2half(W[i]);
    }

    // ---- P1: gather + mean, write f16 A rows ---------------------------------
    const uint2* __restrict__ feat = layer2 ? (const uint2*)g_hh
                                            : (const uint2*)g_xh;
    for (int r = wid; r < TILE_M; r += TW) {
        int node = n0 + r;
        float4 acc = make_float4(0.f, 0.f, 0.f, 0.f);
        if (node < NN) {
            int beg = g_off[node], end = g_off[node + 1];
            int e0 = beg;
            for (; e0 + 32 <= end; e0 += 32) {
                int myid = g_esrc[e0 + lane];
#pragma unroll 8
                for (int j = 0; j < 32; ++j) {
                    int sid = __shfl_sync(0xffffffffu, myid, j);
                    uint2 rr = feat[sid * 32 + lane];
                    float2 a = __half22float2(*(__half2*)&rr.x);
                    float2 bb = __half22float2(*(__half2*)&rr.y);
                    acc.x += a.x; acc.y += a.y; acc.z += bb.x; acc.w += bb.y;
                }
            }
            int n = end - e0;
            if (n) {
                int myid = (lane < n) ? g_esrc[e0 + lane] : 0;
                for (int j = 0; j < n; ++j) {
                    int sid = __shfl_sync(0xffffffffu, myid, j);
                    uint2 rr = feat[sid * 32 + lane];
                    float2 a = __half22float2(*(__half2*)&rr.x);
                    float2 bb = __half22float2(*(__half2*)&rr.y);
                    acc.x += a.x; acc.y += a.y; acc.z += bb.x; acc.w += bb.y;
                }
            }
            float inv = g_inv[node];
            acc.x *= inv; acc.y *= inv; acc.z *= inv; acc.w *= inv;
        }
        __half2 h0 = __floats2half2_rn(acc.x, acc.y);
        __half2 h1 = __floats2half2_rn(acc.z, acc.w);
        uint2 pk;
        pk.x = *(uint32_t*)&h0;
        pk.y = *(uint32_t*)&h1;
        *(uint2*)&As[r * LDA + 4 * lane] = pk;
    }
    __syncthreads();

    // ---- P2: wmma matmul (warps 0-15, 32x32 blocks) --------------------------
    wmma::fragment<wmma::accumulator, 16, 16, 16, float> accf[2][2];
    if (wid < 16) {
        int mi = (wid >> 2) * 32;     // row block
        int ni = (wid & 3) * 32;      // col block
#pragma unroll
        for (int i = 0; i < 2; ++i)
#pragma unroll
            for (int j = 0; j < 2; ++j) wmma::fill_fragment(accf[i][j], 0.0f);
#pragma unroll
        for (int kk = 0; kk < 8; ++kk) {
            wmma::fragment<wmma::matrix_a, 16, 16, 16, __half, wmma::row_major> af[2];
            wmma::fragment<wmma::matrix_b, 16, 16, 16, __half, wmma::row_major> bf[2];
#pragma unroll
            for (int i = 0; i < 2; ++i)
                wmma::load_matrix_sync(af[i], &As[(mi + 16 * i) * LDA + 16 * kk], LDA);
#pragma unroll
            for (int j = 0; j < 2; ++j)
                wmma::load_matrix_sync(bf[j], &Bs[(16 * kk) * LDB + ni + 16 * j], LDB);
#pragma unroll
            for (int i = 0; i < 2; ++i)
#pragma unroll
                for (int j = 0; j < 2; ++j)
                    wmma::mma_sync(accf[i][j], af[i], bf[j], accf[i][j]);
        }
    }
    __syncthreads();                  // all A/B reads done before C overlays
    if (wid < 16) {
        int mi = (wid >> 2) * 32;
        int ni = (wid & 3) * 32;
#pragma unroll
        for (int i = 0; i < 2; ++i)
#pragma unroll
            for (int j = 0; j < 2; ++j)
                wmma::store_matrix_sync(&Cs[(mi + 16 * i) * LDC + ni + 16 * j],
                                        accf[i][j], LDC, wmma::mem_row_major);
    }
    __syncthreads();

    // ---- P3: epilogue ---------------------------------------------------------
    if (!layer2) {
        // bias + relu -> f16 -> g_hh (coalesced half2 stores)
        __half2* o = (__half2*)g_hh;
        for (int i = tid; i < TILE_M * 64; i += TTH) {
            int r = i >> 6, cp = i & 63;
            int node = n0 + r;
            if (node < NN) {
                float v0 = fmaxf(Cs[r * LDC + 2 * cp]     + biasS[2 * cp],     0.f);
                float v1 = fmaxf(Cs[r * LDC + 2 * cp + 1] + biasS[2 * cp + 1], 0.f);
                o[node * 64 + cp] = __floats2half2_rn(v0, v1);
            }
        }
    } else {
        // bias + relu + W3 projection (128->2), warp per row
        float b30 = b3[0], b31 = b3[1];
        for (int r = wid; r < TILE_M; r += TW) {
            int node = n0 + r;
            float o0 = 0.f, o1 = 0.f;
#pragma unroll
            for (int q = 0; q < 4; ++q) {
                int c = 4 * lane + q;
                float v = fmaxf(Cs[r * LDC + c] + biasS[c], 0.f);
                float2 w3 = w3S[c];
                o0 += v * w3.x;
                o1 += v * w3.y;
            }
#pragma unroll
            for (int d = 16; d; d >>= 1) {
                o0 += __shfl_down_sync(0xffffffffu, o0, d);
                o1 += __shfl_down_sync(0xffffffffu, o1, d);
            }
            if (lane == 0 && node < NN) {
                out[node * 2 + 0] = o0 + b30;
                out[node * 2 + 1] = o1 + b31;
            }
        }
    }
}

// ---------------- launch -----------------------------------------------------
extern "C" void kernel_launch(void* const* d_in, const int* in_sizes, int n_in,
                              void* d_out, int out_size) {
    const float* x  = (const float*)d_in[0];
    const void*  ei = d_in[1];
    const float* W1 = (const float*)d_in[2];
    const float* b1 = (const float*)d_in[3];
    const float* W2 = (const float*)d_in[4];
    const float* b2 = (const float*)d_in[5];
    const float* W3 = (const float*)d_in[6];
    const float* b3 = (const float*)d_in[7];
    float* out = (float*)d_out;

    cudaFuncSetAttribute(k_tile, cudaFuncAttributeMaxDynamicSharedMemorySize,
                         TILE_DSMEM);

    const int TB = 256;
    k_prep<<<NN * F / 4 / TB, TB>>>(ei, (const float4*)x);   // 2500 blocks
    k_scanA<<<NB, 128>>>();
    k_scanB<<<NB, 192>>>();
    k_fill<<<(NE / 8 + TB - 1) / TB, TB>>>(ei);
    k_tile<<<NTILES, TTH, TILE_DSMEM>>>(W1, b1, W3, b3, out, 0);
    k_tile<<<NTILES, TTH, TILE_DSMEM>>>(W2, b2, W3, b3, out, 1);
}

// round 17
// speedup vs baseline: 2.3615x; 1.1704x over previous
#include <cuda_runtime.h>
#include <cuda_fp16.h>
#include <mma.h>
#include <cstdint>

#define NN 20000
#define NE 640000
#define F  128
#define NB 160                    // scan blocks
#define CH 125                    // elements per scan block (160*125 = 20000)

#define TILE_M   160              // 160*125 = 20000 exactly, one wave of 125 CTAs
#define NTILES   125
#define TW       20               // warps in k_tile
#define TTH      (TW * 32)        // 640 threads
#define LDA      136              // padded f16 leading dims (17*8)
#define LDB      136
#define LDC      132              // padded f32 leading dim (33*4)
// smem layout
#define SM_BIAS  0                // 128 f32
#define SM_W3    1024             // 128 float2
#define SM_A     2048             // 160x136 f16 = 43520 B
#define SM_B     45568            // 128x136 f16 = 34816 B
#define SM_C     2048             // f32 C overlays A/B after MMA (160x132x4 = 84480 B)
#define TILE_DSMEM 86528

// ---------------- scratch (device globals; no allocations allowed) ----------
__device__ __align__(16) __half g_xh[NN * F];    // x in f16 (gather source L1)
__device__ __align__(16) __half g_hh[NN * F];    // h1 in f16 (gather source L2)
__device__ float g_inv[NN];       // 1 / max(indegree, 1)
__device__ int   g_cnt[NN];       // zero at start; scanB re-zeroes each call
__device__ int   g_off[NN + 1];   // CSR offsets by dst
__device__ __align__(16) int g_tkt[NE];   // per-edge ticket within its dst segment
__device__ int   g_esrc[NE];      // src ids grouped by dst
__device__ int   g_bsum[NB];      // per-block count sums

// Per-block int64 detection: int64 node ids < 2^31 have zero high words at odd
// int32 indices; int32 data has uniform node ids there.
__device__ __forceinline__ int block_is64(const int* __restrict__ ei32,
                                          int* __restrict__ s64) {
    if (threadIdx.x < 32) {
        int v = 0;
#pragma unroll
        for (int j = 0; j < 4; ++j) v |= ei32[2 * (threadIdx.x + 32 * j) + 1];
#pragma unroll
        for (int d = 16; d; d >>= 1) v |= __shfl_xor_sync(0xffffffffu, v, d);
        if (threadIdx.x == 0) *s64 = (v == 0) ? 1 : 0;
    }
    __syncthreads();
    return *s64;
}

// ---------------- prep: x->f16 + count with saved tickets --------------------
__global__ void k_prep(const void* __restrict__ ei, const float4* __restrict__ x) {
    __shared__ int s64;
    int is64 = block_is64((const int*)ei, &s64);
    int i = blockIdx.x * blockDim.x + threadIdx.x;   // < 640000 exactly
    float4 v = x[i];
    __half2* o = (__half2*)g_xh;
    o[2 * i + 0] = __floats2half2_rn(v.x, v.y);
    o[2 * i + 1] = __floats2half2_rn(v.z, v.w);

    int dst = is64 ? (int)((const long long*)ei)[NE + i]
                   : ((const int*)ei)[NE + i];
    if ((unsigned)dst < NN) g_tkt[i] = atomicAdd(&g_cnt[dst], 1);
}

// ---------------- hierarchical scan (grid=160) --------------------------------
__global__ void __launch_bounds__(128) k_scanA() {
    int b = blockIdx.x, t = threadIdx.x, lane = t & 31, wid = t >> 5;
    __shared__ int ws[4];
    int c = (t < CH) ? g_cnt[b * CH + t] : 0;
#pragma unroll
    for (int d = 16; d; d >>= 1) c += __shfl_xor_sync(0xffffffffu, c, d);
    if (lane == 0) ws[wid] = c;
    __syncthreads();
    if (t == 0) g_bsum[b] = ws[0] + ws[1] + ws[2] + ws[3];
}

__global__ void __launch_bounds__(192) k_scanB() {
    int b = blockIdx.x, t = threadIdx.x, lane = t & 31, wid = t >> 5;
    __shared__ int bs[6];
    __shared__ int wsum[4];
    int v = (t < b) ? g_bsum[t] : 0;
#pragma unroll
    for (int d = 16; d; d >>= 1) v += __shfl_xor_sync(0xffffffffu, v, d);
    if (lane == 0) bs[wid] = v;
    __syncthreads();
    int base = bs[0] + bs[1] + bs[2] + bs[3] + bs[4] + bs[5];

    int i = b * CH + t;
    int c = (t < CH) ? g_cnt[i] : 0;
    int s = c;
#pragma unroll
    for (int d = 1; d < 32; d <<= 1) {
        int u = __shfl_up_sync(0xffffffffu, s, d);
        if (lane >= d) s += u;
    }
    if (lane == 31 && wid < 4) wsum[wid] = s;
    __syncthreads();
    int off = base;
#pragma unroll
    for (int w = 0; w < 4; ++w) off += (w < wid) ? wsum[w] : 0;
    if (t < CH) {
        int inc = off + s;
        g_off[i + 1] = inc;
        g_inv[i]     = 1.0f / (float)(c > 0 ? c : 1);
        g_cnt[i]     = 0;
    }
    if (b == 0 && t == 0) g_off[0] = 0;
}

// ---------------- fill: atomic-free, 4 edges per thread -----------------------
__global__ void k_fill(const void* __restrict__ ei) {
    __shared__ int s64;
    int is64 = block_is64((const int*)ei, &s64);
    int t = blockIdx.x * blockDim.x + threadIdx.x;
    if (t >= NE / 4) return;
    int e0 = t * 4;
    int s[4], d[4], tk[4];
    if (is64) {
        const longlong2* p = (const longlong2*)ei;
        longlong2 a = p[e0 / 2],        b = p[e0 / 2 + 1];
        longlong2 c = p[(NE + e0) / 2], e = p[(NE + e0) / 2 + 1];
        s[0] = (int)a.x; s[1] = (int)a.y; s[2] = (int)b.x; s[3] = (int)b.y;
        d[0] = (int)c.x; d[1] = (int)c.y; d[2] = (int)e.x; d[3] = (int)e.y;
    } else {
        const int4* p = (const int4*)ei;
        int4 a = p[e0 / 4];
        int4 c = p[(NE + e0) / 4];
        s[0] = a.x; s[1] = a.y; s[2] = a.z; s[3] = a.w;
        d[0] = c.x; d[1] = c.y; d[2] = c.z; d[3] = c.w;
    }
    {
        int4 a = ((const int4*)g_tkt)[e0 / 4];
        tk[0] = a.x; tk[1] = a.y; tk[2] = a.z; tk[3] = a.w;
    }
    int base[4];
#pragma unroll
    for (int j = 0; j < 4; ++j)
        base[j] = ((unsigned)d[j] < NN) ? g_off[d[j]] : -1;
#pragma unroll
    for (int j = 0; j < 4; ++j)
        if (base[j] >= 0 && (unsigned)s[j] < NN)
            g_esrc[base[j] + tk[j]] = s[j];
}

// ---------------- tile layer: gather -> wmma (HMMA) -> epilogue ---------------
// Grid NTILES=125, 640 threads, 1 CTA/SM — one perfectly balanced wave.
// P1: all 20 warps gather+mean f16 rows (8 each) into A [160][LDA].
// P2: all 20 warps compute 32x32 output blocks (5x4 grid) via wmma f16->f32.
// P3: epilogue; layer1: bias+relu -> f16 g_hh; layer2: +W3 projection -> out.
__global__ void __launch_bounds__(TTH, 1) k_tile(
    const float* __restrict__ W,  const float* __restrict__ bias,
    const float* __restrict__ W3, const float* __restrict__ b3,
    float* __restrict__ out, int layer2)
{
    using namespace nvcuda;
    extern __shared__ char smem[];
    int tid = threadIdx.x, wid = tid >> 5, lane = tid & 31;
    int n0 = blockIdx.x * TILE_M;

    float*  biasS = (float*)(smem + SM_BIAS);
    float2* w3S   = (float2*)(smem + SM_W3);
    __half* As    = (__half*)(smem + SM_A);
    __half* Bs    = (__half*)(smem + SM_B);
    float*  Cs    = (float*)(smem + SM_C);

    // ---- P0: stage bias / W3 / B = W (f16, row-major [k][j]) -----------------
    if (tid < 128) biasS[tid] = bias[tid];
    if (layer2 && tid < 128) w3S[tid] = ((const float2*)W3)[tid];
    for (int i = tid; i < F * F; i += TTH) {
        int k = i >> 7, j = i & 127;
        Bs[k * LDB + j] = __float2half(W[i]);
    }

    // ---- P1: gather + mean, write f16 A rows ---------------------------------
    const uint2* __restrict__ feat = layer2 ? (const uint2*)g_hh
                                            : (const uint2*)g_xh;
    for (int r = wid; r < TILE_M; r += TW) {
        int node = n0 + r;                    // < NN always (160*125 = 20000)
        float4 acc = make_float4(0.f, 0.f, 0.f, 0.f);
        int beg = g_off[node], end = g_off[node + 1];
        int e0 = beg;
        for (; e0 + 32 <= end; e0 += 32) {
            int myid = g_esrc[e0 + lane];
#pragma unroll 8
            for (int j = 0; j < 32; ++j) {
                int sid = __shfl_sync(0xffffffffu, myid, j);
                uint2 rr = feat[sid * 32 + lane];
                float2 a = __half22float2(*(__half2*)&rr.x);
                float2 bb = __half22float2(*(__half2*)&rr.y);
                acc.x += a.x; acc.y += a.y; acc.z += bb.x; acc.w += bb.y;
            }
        }
        int n = end - e0;
        if (n) {
            int myid = (lane < n) ? g_esrc[e0 + lane] : 0;
            for (int j = 0; j < n; ++j) {
                int sid = __shfl_sync(0xffffffffu, myid, j);
                uint2 rr = feat[sid * 32 + lane];
                float2 a = __half22float2(*(__half2*)&rr.x);
                float2 bb = __half22float2(*(__half2*)&rr.y);
                acc.x += a.x; acc.y += a.y; acc.z += bb.x; acc.w += bb.y;
            }
        }
        float inv = g_inv[node];
        acc.x *= inv; acc.y *= inv; acc.z *= inv; acc.w *= inv;
        __half2 h0 = __floats2half2_rn(acc.x, acc.y);
        __half2 h1 = __floats2half2_rn(acc.z, acc.w);
        uint2 pk;
        pk.x = *(uint32_t*)&h0;
        pk.y = *(uint32_t*)&h1;
        *(uint2*)&As[r * LDA + 4 * lane] = pk;
    }
    __syncthreads();

    // ---- P2: wmma matmul (all 20 warps, 5x4 grid of 32x32 blocks) ------------
    wmma::fragment<wmma::accumulator, 16, 16, 16, float> accf[2][2];
    {
        int mi = (wid >> 2) * 32;     // 0..4 row blocks (160)
        int ni = (wid & 3) * 32;      // 0..3 col blocks (128)
#pragma unroll
        for (int i = 0; i < 2; ++i)
#pragma unroll
            for (int j = 0; j < 2; ++j) wmma::fill_fragment(accf[i][j], 0.0f);
#pragma unroll
        for (int kk = 0; kk < 8; ++kk) {
            wmma::fragment<wmma::matrix_a, 16, 16, 16, __half, wmma::row_major> af[2];
            wmma::fragment<wmma::matrix_b, 16, 16, 16, __half, wmma::row_major> bf[2];
#pragma unroll
            for (int i = 0; i < 2; ++i)
                wmma::load_matrix_sync(af[i], &As[(mi + 16 * i) * LDA + 16 * kk], LDA);
#pragma unroll
            for (int j = 0; j < 2; ++j)
                wmma::load_matrix_sync(bf[j], &Bs[(16 * kk) * LDB + ni + 16 * j], LDB);
#pragma unroll
            for (int i = 0; i < 2; ++i)
#pragma unroll
                for (int j = 0; j < 2; ++j)
                    wmma::mma_sync(accf[i][j], af[i], bf[j], accf[i][j]);
        }
    }
    __syncthreads();                  // all A/B reads done before C overlays
    {
        int mi = (wid >> 2) * 32;
        int ni = (wid & 3) * 32;
#pragma unroll
        for (int i = 0; i < 2; ++i)
#pragma unroll
            for (int j = 0; j < 2; ++j)
                wmma::store_matrix_sync(&Cs[(mi + 16 * i) * LDC + ni + 16 * j],
                                        accf[i][j], LDC, wmma::mem_row_major);
    }
    __syncthreads();

    // ---- P3: epilogue ---------------------------------------------------------
    if (!layer2) {
        // bias + relu -> f16 -> g_hh (coalesced half2 stores)
        __half2* o = (__half2*)g_hh;
        for (int i = tid; i < TILE_M * 64; i += TTH) {
            int r = i >> 6, cp = i & 63;
            int node = n0 + r;
            float v0 = fmaxf(Cs[r * LDC + 2 * cp]     + biasS[2 * cp],     0.f);
            float v1 = fmaxf(Cs[r * LDC + 2 * cp + 1] + biasS[2 * cp + 1], 0.f);
            o[node * 64 + cp] = __floats2half2_rn(v0, v1);
        }
    } else {
        // bias + relu + W3 projection (128->2), warp per row
        float b30 = b3[0], b31 = b3[1];
        for (int r = wid; r < TILE_M; r += TW) {
            int node = n0 + r;
            float o0 = 0.f, o1 = 0.f;
#pragma unroll
            for (int q = 0; q < 4; ++q) {
                int c = 4 * lane + q;
                float v = fmaxf(Cs[r * LDC + c] + biasS[c], 0.f);
                float2 w3 = w3S[c];
                o0 += v * w3.x;
                o1 += v * w3.y;
            }
#pragma unroll
            for (int d = 16; d; d >>= 1) {
                o0 += __shfl_down_sync(0xffffffffu, o0, d);
                o1 += __shfl_down_sync(0xffffffffu, o1, d);
            }
            if (lane == 0) {
                out[node * 2 + 0] = o0 + b30;
                out[node * 2 + 1] = o1 + b31;
            }
        }
    }
}

// ---------------- launch -----------------------------------------------------
extern "C" void kernel_launch(void* const* d_in, const int* in_sizes, int n_in,
                              void* d_out, int out_size) {
    const float* x  = (const float*)d_in[0];
    const void*  ei = d_in[1];
    const float* W1 = (const float*)d_in[2];
    const float* b1 = (const float*)d_in[3];
    const float* W2 = (const float*)d_in[4];
    const float* b2 = (const float*)d_in[5];
    const float* W3 = (const float*)d_in[6];
    const float* b3 = (const float*)d_in[7];
    float* out = (float*)d_out;

    cudaFuncSetAttribute(k_tile, cudaFuncAttributeMaxDynamicSharedMemorySize,
                         TILE_DSMEM);

    const int TB = 256;
    k_prep<<<NN * F / 4 / TB, TB>>>(ei, (const float4*)x);   // 2500 blocks
    k_scanA<<<NB, 128>>>();
    k_scanB<<<NB, 192>>>();
    k_fill<<<(NE / 4 + TB - 1) / TB, TB>>>(ei);
    k_tile<<<NTILES, TTH, TILE_DSMEM>>>(W1, b1, W3, b3, out, 0);
    k_tile<<<NTILES, TTH, TILE_DSMEM>>>(W2, b2, W3, b3, out, 1);
}